// round 7
// baseline (speedup 1.0000x reference)
#include <cuda_runtime.h>
#include <cstdint>
#include <math.h>

#define EPSI 1e-5f
#define GAMMA_C 1.3f

typedef unsigned long long u64t;

__device__ __forceinline__ u64t splat2(float a) {
    u64t r; asm("mov.b64 %0, {%1, %1};" : "=l"(r) : "f"(a)); return r;
}
__device__ __forceinline__ void fma2(u64t& d, u64t a, u64t b) {
    asm("fma.rn.f32x2 %0, %1, %2, %0;" : "+l"(d) : "l"(a), "l"(b));
}
__device__ __forceinline__ void unpack2(u64t v, float& lo, float& hi) {
    asm("mov.b64 {%0, %1}, %2;" : "=f"(lo), "=f"(hi) : "l"(v));
}
__device__ __forceinline__ void cp16(unsigned int dst, const void* src) {
    asm volatile("cp.async.cg.shared.global [%0], [%1], 16;" :: "r"(dst), "l"(src));
}

__device__ __forceinline__ float f4c(const float4& v, int i) {
    switch (i & 3) {
        case 0: return v.x;
        case 1: return v.y;
        case 2: return v.z;
        default: return v.w;
    }
}

// Block GEMM: C[16 x 256] = A[16 x KTOT] (smem, stride lda) * W[KTOT x 256]
// (global, row stride ldw). 256 threads, 8 warps; 2 blocks resident per SM.
// Warp w owns float cols [16w, 16w+16) of each 128-col half.
// Lane: rp = lane&3 -> rows rp + {0,4,8,12}; cp = lane>>2 -> col pair c0 = 16w + 2cp.
// Thread tile: 4 rows x 4 cols {c0, c0+1, c0+128, c0+129} (GLU pairs in-thread).
// Per k per thread: 2x LDS.64 (W), 4 splats, 8 FFMA2. W bytes/FFMA2 = 2.0.
// Weights streamed through double-buffered 8-row chunks via cp.async.
template <int KTOT, typename Epi>
__device__ __forceinline__ void gemm_tile(
    const float* __restrict__ As, int lda,
    const float* __restrict__ Wg, int ldw,
    float* __restrict__ wbuf, Epi epi)
{
    const int tid  = threadIdx.x;
    const int wid  = tid >> 5, lane = tid & 31;
    const int rp   = lane & 3, cp = lane >> 2;
    const int c0   = wid * 16 + cp * 2;
    constexpr int NCH = KTOT / 8;

    u64t acc[4][2];
#pragma unroll
    for (int i = 0; i < 4; i++) { acc[i][0] = 0ull; acc[i][1] = 0ull; }

    const unsigned int wb_s = (unsigned int)__cvta_generic_to_shared(wbuf);

    // prefetch chunk 0 (8 rows x 256 cols = 512 float4, 2 per thread)
#pragma unroll
    for (int i2 = 0; i2 < 2; i2++) {
        int f2 = tid + 256 * i2;
        int k = f2 >> 6, c = f2 & 63;
        cp16(wb_s + f2 * 16, Wg + k * ldw + c * 4);
    }
    asm volatile("cp.async.commit_group;" ::: "memory");
    asm volatile("cp.async.wait_group 0;" ::: "memory");
    __syncthreads();

    int cur = 0;
    for (int ch = 0; ch < NCH; ch++) {
        const bool more = (ch + 1 < NCH);
        if (more) {
            const float* Wn = Wg + (ch + 1) * 8 * ldw;
#pragma unroll
            for (int i2 = 0; i2 < 2; i2++) {
                int f2 = tid + 256 * i2;
                int k = f2 >> 6, c = f2 & 63;
                cp16(wb_s + (cur ^ 1) * 8192 + f2 * 16, Wn + k * ldw + c * 4);
            }
            asm volatile("cp.async.commit_group;" ::: "memory");
        }
        const float* wc = wbuf + cur * 2048;
        const int kk = ch * 8;
#pragma unroll
        for (int k4 = 0; k4 < 2; k4++) {
            float4 a[4];
#pragma unroll
            for (int i = 0; i < 4; i++)
                a[i] = *reinterpret_cast<const float4*>(
                    As + (rp + 4 * i) * lda + kk + k4 * 4);
#pragma unroll
            for (int kz = 0; kz < 4; kz++) {
                const float* wr = wc + (k4 * 4 + kz) * 256;
                u64t w0 = *reinterpret_cast<const u64t*>(wr + c0);
                u64t w1 = *reinterpret_cast<const u64t*>(wr + c0 + 128);
#pragma unroll
                for (int i = 0; i < 4; i++) {
                    u64t s = splat2(f4c(a[i], kz));
                    fma2(acc[i][0], s, w0);
                    fma2(acc[i][1], s, w1);
                }
            }
        }
        if (more) asm volatile("cp.async.wait_group 0;" ::: "memory");
        __syncthreads();
        cur ^= 1;
    }
    epi(rp, c0, acc);
}

#define XS_LD 516
#define SH_LD 132
#define ROWS 16

__global__ __launch_bounds__(256, 2)
void tabnet_kernel(
    const float* __restrict__ x,
    const float* __restrict__ bn0_g, const float* __restrict__ bn0_b,
    const float* __restrict__ bn0_m, const float* __restrict__ bn0_v,
    const float* __restrict__ shW,
    const float* __restrict__ sh_g, const float* __restrict__ sh_b,
    const float* __restrict__ sh_m, const float* __restrict__ sh_v,
    const float* __restrict__ stW,
    const float* __restrict__ st_g, const float* __restrict__ st_b,
    const float* __restrict__ st_m, const float* __restrict__ st_v,
    const float* __restrict__ atW,
    const float* __restrict__ at_g, const float* __restrict__ at_b,
    const float* __restrict__ at_m, const float* __restrict__ at_v,
    const float* __restrict__ fW, const float* __restrict__ fb,
    float* __restrict__ out)
{
    extern __shared__ float smem[];
    float* xs    = smem;             // [16][516]  x tile, later z buffer
    float* prior = smem + 8256;      // [16][512]
    float* shb   = smem + 16448;     // [16][132]  GLU(shared step) output
    float* hg    = smem + 18560;     // [16][132]  GLU(step) output (h_d | h_a)
    float* aggs  = smem + 20672;     // [16][64]
    float* wbuf  = smem + 21696;     // 2 x [8][256] weight chunks
    float* bnsc  = smem + 25792;     // [512]
    float* bnsh  = smem + 26304;     // [512]
    // total 26816 floats = 107264 bytes -> 2 blocks/SM

    const int tid = threadIdx.x;
    const int row0 = blockIdx.x << 4;

    for (int i = tid; i < ROWS * 64; i += 256) aggs[i] = 0.f;

    for (int c = tid; c < 512; c += 256) {
        float sc = bn0_g[c] * rsqrtf(bn0_v[c] + EPSI);
        bnsc[c] = sc;
        bnsh[c] = bn0_b[c] - bn0_m[c] * sc;
    }
    __syncthreads();

    // load x tile + bn0
    {
        const float4* xg = reinterpret_cast<const float4*>(x) + (size_t)row0 * 128;
        const float4* s4 = reinterpret_cast<const float4*>(bnsc);
        const float4* b4 = reinterpret_cast<const float4*>(bnsh);
        float4* xs4 = reinterpret_cast<float4*>(xs);
#pragma unroll
        for (int i = 0; i < 8; i++) {
            int f = tid + 256 * i;
            int r = f >> 7, c4 = f & 127;
            float4 v = xg[f];
            float4 s = s4[c4], b = b4[c4];
            v.x = fmaf(v.x, s.x, b.x);
            v.y = fmaf(v.y, s.y, b.y);
            v.z = fmaf(v.z, s.z, b.z);
            v.w = fmaf(v.w, s.w, b.w);
            xs4[r * 129 + c4] = v;
        }
    }
    __syncthreads();

    // shared-step bn tables
    {
        int c = tid;
        float sc = sh_g[c] * rsqrtf(sh_v[c] + EPSI);
        bnsc[c] = sc;
        bnsh[c] = sh_b[c] - sh_m[c] * sc;
    }

    // GEMM1: sh = GLU(bn(x @ shW))
    gemm_tile<512>(xs, XS_LD, shW, 256, wbuf,
        [&](int rb, int c0, u64t (&acc)[4][2]) {
#pragma unroll
            for (int i = 0; i < 4; i++) {
                int row = rb + 4 * i;
                float u[2], w[2];
                unpack2(acc[i][0], u[0], u[1]);
                unpack2(acc[i][1], w[0], w[1]);
#pragma unroll
                for (int t = 0; t < 2; t++) {
                    int cu = c0 + t, cw = c0 + 128 + t;
                    float uu = fmaf(u[t], bnsc[cu], bnsh[cu]);
                    float ww = fmaf(w[t], bnsc[cw], bnsh[cw]);
                    shb[row * SH_LD + cu] = uu / (1.f + __expf(-ww));
                }
            }
        });
    __syncthreads();

    for (int s = 0; s < 3; s++) {
        {
            int c = tid;
            float sc = st_g[s * 256 + c] * rsqrtf(st_v[s * 256 + c] + EPSI);
            bnsc[c] = sc;
            bnsh[c] = st_b[s * 256 + c] - st_m[s * 256 + c] * sc;
        }
        // GEMM2: h = GLU(bn(sh @ stW[s])); agg += h_d
        gemm_tile<128>(shb, SH_LD, stW + s * 128 * 256, 256, wbuf,
            [&](int rb, int c0, u64t (&acc)[4][2]) {
#pragma unroll
                for (int i = 0; i < 4; i++) {
                    int row = rb + 4 * i;
                    float u[2], w[2];
                    unpack2(acc[i][0], u[0], u[1]);
                    unpack2(acc[i][1], w[0], w[1]);
#pragma unroll
                    for (int t = 0; t < 2; t++) {
                        int cu = c0 + t, cw = c0 + 128 + t;
                        float uu = fmaf(u[t], bnsc[cu], bnsh[cu]);
                        float ww = fmaf(w[t], bnsc[cw], bnsh[cw]);
                        float val = uu / (1.f + __expf(-ww));
                        hg[row * SH_LD + cu] = val;
                        if (c0 < 64) aggs[row * 64 + cu] += val;
                    }
                }
            });
        __syncthreads();
        if (s == 2) break;  // last step's attention/sparsemax/prior are dead code

        for (int c = tid; c < 512; c += 256) {
            float sc = at_g[s * 512 + c] * rsqrtf(at_v[s * 512 + c] + EPSI);
            bnsc[c] = sc;
            bnsh[c] = at_b[s * 512 + c] - at_m[s * 512 + c] * sc;
        }
        // GEMM3: z = bn(h_a @ atW[s]) * prior -> xs
        for (int half = 0; half < 2; half++) {
            const int cbase = half * 256;
            gemm_tile<64>(hg + 64, SH_LD, atW + s * 64 * 512 + cbase, 512, wbuf,
                [&](int rb, int c0, u64t (&acc)[4][2]) {
#pragma unroll
                    for (int i = 0; i < 4; i++) {
                        int row = rb + 4 * i;
                        float u[2], w[2];
                        unpack2(acc[i][0], u[0], u[1]);
                        unpack2(acc[i][1], w[0], w[1]);
#pragma unroll
                        for (int t = 0; t < 2; t++) {
                            int col = cbase + c0 + t;
                            float z = fmaf(u[t], bnsc[col], bnsh[col]);
                            float p = (s == 0) ? 1.f : prior[row * 512 + col];
                            xs[row * XS_LD + col] = z * p;
                            int col2 = cbase + c0 + 128 + t;
                            float z2 = fmaf(w[t], bnsc[col2], bnsh[col2]);
                            float p2 = (s == 0) ? 1.f : prior[row * 512 + col2];
                            xs[row * XS_LD + col2] = z2 * p2;
                        }
                    }
                });
        }
        __syncthreads();

        // sparsemax (Newton on tau) + prior update; warp w -> rows 2w, 2w+1
        {
            const int wid = tid >> 5, lane = tid & 31;
            const int mm0 = wid << 1;
            for (int r = 0; r < 2; r++) {
                const int row = mm0 + r;
                const float4* zp = reinterpret_cast<const float4*>(xs + row * XS_LD);
                float4 zv[4];
#pragma unroll
                for (int j = 0; j < 4; j++) zv[j] = zp[lane + 32 * j];
                float ssum = 0.f;
#pragma unroll
                for (int j = 0; j < 4; j++) ssum += zv[j].x + zv[j].y + zv[j].z + zv[j].w;
#pragma unroll
                for (int off = 16; off; off >>= 1)
                    ssum += __shfl_xor_sync(0xffffffffu, ssum, off);
                float tau = (ssum - 1.f) * (1.f / 512.f);
                for (int it = 0; it < 64; it++) {
                    float sb = 0.f, cb = 0.f;
#pragma unroll
                    for (int j = 0; j < 4; j++) {
                        float d;
                        d = zv[j].x - tau; if (d > 0.f) { sb += d; cb += 1.f; }
                        d = zv[j].y - tau; if (d > 0.f) { sb += d; cb += 1.f; }
                        d = zv[j].z - tau; if (d > 0.f) { sb += d; cb += 1.f; }
                        d = zv[j].w - tau; if (d > 0.f) { sb += d; cb += 1.f; }
                    }
#pragma unroll
                    for (int off = 16; off; off >>= 1) {
                        sb += __shfl_xor_sync(0xffffffffu, sb, off);
                        cb += __shfl_xor_sync(0xffffffffu, cb, off);
                    }
                    float tn = tau + (sb - 1.f) / cb;
                    if (!(tn > tau)) break;
                    tau = tn;
                }
                float4* pp = reinterpret_cast<float4*>(prior + row * 512);
#pragma unroll
                for (int j = 0; j < 4; j++) {
                    float4 pv = (s == 0) ? make_float4(1.f, 1.f, 1.f, 1.f)
                                         : pp[lane + 32 * j];
                    float4 o;
                    o.x = pv.x * (GAMMA_C - fmaxf(zv[j].x - tau, 0.f));
                    o.y = pv.y * (GAMMA_C - fmaxf(zv[j].y - tau, 0.f));
                    o.z = pv.z * (GAMMA_C - fmaxf(zv[j].z - tau, 0.f));
                    o.w = pv.w * (GAMMA_C - fmaxf(zv[j].w - tau, 0.f));
                    pp[lane + 32 * j] = o;
                }
            }
        }
        __syncthreads();
    }

    __syncthreads();
    // final: out = agg @ fW + fb
    if (tid < 32) {
        int m = tid >> 1, o = tid & 1;
        float acc = fb[o];
#pragma unroll
        for (int j = 0; j < 64; j++) acc = fmaf(aggs[m * 64 + j], fW[j * 2 + o], acc);
        out[(size_t)(row0 + m) * 2 + o] = acc;
    }
}

extern "C" void kernel_launch(void* const* d_in, const int* in_sizes, int n_in,
                              void* d_out, int out_size)
{
    const float* x    = (const float*)d_in[0];
    const float* bn0g = (const float*)d_in[1];
    const float* bn0b = (const float*)d_in[2];
    const float* bn0m = (const float*)d_in[3];
    const float* bn0v = (const float*)d_in[4];
    const float* shW  = (const float*)d_in[5];
    const float* shg  = (const float*)d_in[6];
    const float* shbp = (const float*)d_in[7];
    const float* shm  = (const float*)d_in[8];
    const float* shv  = (const float*)d_in[9];
    const float* stW  = (const float*)d_in[10];
    const float* stg  = (const float*)d_in[11];
    const float* stb  = (const float*)d_in[12];
    const float* stm  = (const float*)d_in[13];
    const float* stv  = (const float*)d_in[14];
    const float* atW  = (const float*)d_in[15];
    const float* atg  = (const float*)d_in[16];
    const float* atb  = (const float*)d_in[17];
    const float* atm  = (const float*)d_in[18];
    const float* atv  = (const float*)d_in[19];
    const float* fW   = (const float*)d_in[20];
    const float* fb   = (const float*)d_in[21];

    int Btot = in_sizes[0] / 512;
    int grid = Btot / 16;
    size_t smem = 26816 * sizeof(float);
    cudaFuncSetAttribute(tabnet_kernel,
                         cudaFuncAttributeMaxDynamicSharedMemorySize, (int)smem);
    tabnet_kernel<<<grid, 256, smem>>>(
        x, bn0g, bn0b, bn0m, bn0v,
        shW, shg, shbp, shm, shv,
        stW, stg, stb, stm, stv,
        atW, atg, atb, atm, atv,
        fW, fb, (float*)d_out);
}

// round 8
// speedup vs baseline: 1.8820x; 1.8820x over previous
#include <cuda_runtime.h>
#include <cstdint>
#include <math.h>

#define EPSI 1e-5f
#define GAMMA_C 1.3f

typedef unsigned long long u64t;

__device__ __forceinline__ u64t splat2(float a) {
    u64t r; asm("mov.b64 %0, {%1, %1};" : "=l"(r) : "f"(a)); return r;
}
__device__ __forceinline__ void fma2(u64t& d, u64t a, u64t b) {
    asm("fma.rn.f32x2 %0, %1, %2, %0;" : "+l"(d) : "l"(a), "l"(b));
}
__device__ __forceinline__ void unpack2(u64t v, float& lo, float& hi) {
    asm("mov.b64 {%0, %1}, %2;" : "=f"(lo), "=f"(hi) : "l"(v));
}
__device__ __forceinline__ void cp16(unsigned int dst, const void* src) {
    asm volatile("cp.async.cg.shared.global [%0], [%1], 16;" :: "r"(dst), "l"(src));
}

__device__ __forceinline__ float f4c(const float4& v, int i) {
    switch (i & 3) {
        case 0: return v.x;
        case 1: return v.y;
        case 2: return v.z;
        default: return v.w;
    }
}

// Block GEMM: C[32 x 256] = A[32 x KTOT] (smem, stride lda) * W[KTOT x 256]
// (global, row stride ldw). 256 threads, 8 warps, ONE block per SM.
// Warp w owns cols [16w,16w+16) and [128+16w,128+16w+16) -> GLU pairs in-warp.
// Each warp streams its OWN 32-col W slice through a warp-private smem double
// buffer (16-k chunks) with its own cp.async groups: NO __syncthreads in the
// mainloop. Lane: rp=lane&3 -> 8 rows rp+4i; cp=lane>>2 -> col pair c0=16w+2cp.
// Thread tile: 8 rows x 4 cols. Per k: 2 LDS.64 (W), 8 splats, 16 FFMA2.
template <int KTOT, typename Epi>
__device__ __forceinline__ void gemm_tile(
    const float* __restrict__ As, int lda,
    const float* __restrict__ Wg, int ldw,
    float* __restrict__ wbuf, Epi epi)
{
    const int tid  = threadIdx.x;
    const int wid  = tid >> 5, lane = tid & 31;
    const int rp   = lane & 3, cp = lane >> 2;
    const int c0   = wid * 16 + cp * 2;
    constexpr int NCH = KTOT / 16;

    // warp-private double buffer: 2 stages x 512 floats (16 k x 32 cols)
    float* wb = wbuf + wid * 1024;
    const unsigned int wb_s = (unsigned int)__cvta_generic_to_shared(wb);

    // decompose lane work for chunk loads: 4 x 16B per lane = 2 KB per chunk
    // flat = lane + 32j; seg = flat>>2 (k 0..15 x half 0..1); part = flat&3
    const int seg0  = lane >> 2;        // 0..7
    const int part  = lane & 3;

    u64t acc[8][2];
#pragma unroll
    for (int i = 0; i < 8; i++) { acc[i][0] = 0ull; acc[i][1] = 0ull; }

    auto load_chunk = [&](int ch, int stage) {
        const float* Wr = Wg + ch * 16 * ldw + wid * 16 + part * 4;
#pragma unroll
        for (int j = 0; j < 4; j++) {
            int seg = seg0 + 8 * j;            // 0..31
            int k = seg >> 1, half = seg & 1;
            cp16(wb_s + stage * 2048 + k * 128 + half * 64 + part * 16,
                 Wr + k * ldw + half * 128);
        }
        asm volatile("cp.async.commit_group;" ::: "memory");
    };

    load_chunk(0, 0);

    int cur = 0;
    for (int ch = 0; ch < NCH; ch++) {
        const bool more = (ch + 1 < NCH);
        if (more) {
            load_chunk(ch + 1, cur ^ 1);
            asm volatile("cp.async.wait_group 1;" ::: "memory");
        } else {
            asm volatile("cp.async.wait_group 0;" ::: "memory");
        }
        const float* wc = wb + cur * 512;
        const int kk = ch * 16;
#pragma unroll
        for (int k4 = 0; k4 < 4; k4++) {
            float4 a[8];
#pragma unroll
            for (int i = 0; i < 8; i++)
                a[i] = *reinterpret_cast<const float4*>(
                    As + (rp + 4 * i) * lda + kk + k4 * 4);
#pragma unroll
            for (int kz = 0; kz < 4; kz++) {
                const float* wr = wc + (k4 * 4 + kz) * 32;
                u64t w0 = *reinterpret_cast<const u64t*>(wr + cp * 2);
                u64t w1 = *reinterpret_cast<const u64t*>(wr + 16 + cp * 2);
#pragma unroll
                for (int i = 0; i < 8; i++) {
                    u64t s = splat2(f4c(a[i], kz));
                    fma2(acc[i][0], s, w0);
                    fma2(acc[i][1], s, w1);
                }
            }
        }
        cur ^= 1;
    }
    epi(rp, c0, acc);
}

#define XS_LD 516
#define SH_LD 132

__global__ __launch_bounds__(256, 1)
void tabnet_kernel(
    const float* __restrict__ x,
    const float* __restrict__ bn0_g, const float* __restrict__ bn0_b,
    const float* __restrict__ bn0_m, const float* __restrict__ bn0_v,
    const float* __restrict__ shW,
    const float* __restrict__ sh_g, const float* __restrict__ sh_b,
    const float* __restrict__ sh_m, const float* __restrict__ sh_v,
    const float* __restrict__ stW,
    const float* __restrict__ st_g, const float* __restrict__ st_b,
    const float* __restrict__ st_m, const float* __restrict__ st_v,
    const float* __restrict__ atW,
    const float* __restrict__ at_g, const float* __restrict__ at_b,
    const float* __restrict__ at_m, const float* __restrict__ at_v,
    const float* __restrict__ fW, const float* __restrict__ fb,
    float* __restrict__ out)
{
    extern __shared__ float smem[];
    float* xs    = smem;             // [32][516]  x tile, later z buffer
    float* prior = smem + 16512;     // [32][512]
    float* shb   = smem + 32896;     // [32][132]  GLU(shared step) output
    float* hg    = smem + 37120;     // [32][132]  GLU(step) output (h_d | h_a)
    float* aggs  = smem + 41344;     // [32][64]
    float* wbuf  = smem + 43392;     // 8 warps x 2 stages x 512 floats
    float* bnsc  = smem + 51584;     // [512]
    float* bnsh  = smem + 52096;     // [512]
    // total 52608 floats = 210432 bytes

    const int tid = threadIdx.x;
    const int row0 = blockIdx.x << 5;

    for (int i = tid; i < 2048; i += 256) aggs[i] = 0.f;

    for (int c = tid; c < 512; c += 256) {
        float sc = bn0_g[c] * rsqrtf(bn0_v[c] + EPSI);
        bnsc[c] = sc;
        bnsh[c] = bn0_b[c] - bn0_m[c] * sc;
    }
    __syncthreads();

    // load x tile + bn0
    {
        const float4* xg = reinterpret_cast<const float4*>(x) + (size_t)row0 * 128;
        const float4* s4 = reinterpret_cast<const float4*>(bnsc);
        const float4* b4 = reinterpret_cast<const float4*>(bnsh);
        float4* xs4 = reinterpret_cast<float4*>(xs);
#pragma unroll
        for (int i = 0; i < 16; i++) {
            int f = tid + 256 * i;
            int r = f >> 7, c4 = f & 127;
            float4 v = xg[f];
            float4 s = s4[c4], b = b4[c4];
            v.x = fmaf(v.x, s.x, b.x);
            v.y = fmaf(v.y, s.y, b.y);
            v.z = fmaf(v.z, s.z, b.z);
            v.w = fmaf(v.w, s.w, b.w);
            xs4[r * 129 + c4] = v;
        }
    }
    __syncthreads();

    // shared-step bn tables
    {
        int c = tid;
        float sc = sh_g[c] * rsqrtf(sh_v[c] + EPSI);
        bnsc[c] = sc;
        bnsh[c] = sh_b[c] - sh_m[c] * sc;
    }
    __syncthreads();   // bn tables visible to all warps' epilogues

    // GEMM1: sh = GLU(bn(x @ shW))
    gemm_tile<512>(xs, XS_LD, shW, 256, wbuf,
        [&](int rp, int c0, u64t (&acc)[8][2]) {
#pragma unroll
            for (int i = 0; i < 8; i++) {
                int row = rp + 4 * i;
                float u[2], w[2];
                unpack2(acc[i][0], u[0], u[1]);
                unpack2(acc[i][1], w[0], w[1]);
#pragma unroll
                for (int t = 0; t < 2; t++) {
                    int cu = c0 + t, cw = c0 + 128 + t;
                    float uu = fmaf(u[t], bnsc[cu], bnsh[cu]);
                    float ww = fmaf(w[t], bnsc[cw], bnsh[cw]);
                    shb[row * SH_LD + cu] = uu / (1.f + __expf(-ww));
                }
            }
        });
    __syncthreads();

    for (int s = 0; s < 3; s++) {
        {
            int c = tid;
            float sc = st_g[s * 256 + c] * rsqrtf(st_v[s * 256 + c] + EPSI);
            bnsc[c] = sc;
            bnsh[c] = st_b[s * 256 + c] - st_m[s * 256 + c] * sc;
        }
        __syncthreads();
        // GEMM2: h = GLU(bn(sh @ stW[s])); agg += h_d
        gemm_tile<128>(shb, SH_LD, stW + s * 128 * 256, 256, wbuf,
            [&](int rp, int c0, u64t (&acc)[8][2]) {
#pragma unroll
                for (int i = 0; i < 8; i++) {
                    int row = rp + 4 * i;
                    float u[2], w[2];
                    unpack2(acc[i][0], u[0], u[1]);
                    unpack2(acc[i][1], w[0], w[1]);
#pragma unroll
                    for (int t = 0; t < 2; t++) {
                        int cu = c0 + t, cw = c0 + 128 + t;
                        float uu = fmaf(u[t], bnsc[cu], bnsh[cu]);
                        float ww = fmaf(w[t], bnsc[cw], bnsh[cw]);
                        float val = uu / (1.f + __expf(-ww));
                        hg[row * SH_LD + cu] = val;
                        if (c0 < 64) aggs[row * 64 + cu] += val;
                    }
                }
            });
        __syncthreads();
        if (s == 2) break;  // last step's attention/sparsemax/prior are dead code

        for (int c = tid; c < 512; c += 256) {
            float sc = at_g[s * 512 + c] * rsqrtf(at_v[s * 512 + c] + EPSI);
            bnsc[c] = sc;
            bnsh[c] = at_b[s * 512 + c] - at_m[s * 512 + c] * sc;
        }
        __syncthreads();
        // GEMM3: z = bn(h_a @ atW[s]) * prior -> xs
        for (int half = 0; half < 2; half++) {
            const int cbase = half * 256;
            gemm_tile<64>(hg + 64, SH_LD, atW + s * 64 * 512 + cbase, 512, wbuf,
                [&](int rp, int c0, u64t (&acc)[8][2]) {
#pragma unroll
                    for (int i = 0; i < 8; i++) {
                        int row = rp + 4 * i;
                        float u[2], w[2];
                        unpack2(acc[i][0], u[0], u[1]);
                        unpack2(acc[i][1], w[0], w[1]);
#pragma unroll
                        for (int t = 0; t < 2; t++) {
                            int col = cbase + c0 + t;
                            float z = fmaf(u[t], bnsc[col], bnsh[col]);
                            float p = (s == 0) ? 1.f : prior[row * 512 + col];
                            xs[row * XS_LD + col] = z * p;
                            int col2 = cbase + c0 + 128 + t;
                            float z2 = fmaf(w[t], bnsc[col2], bnsh[col2]);
                            float p2 = (s == 0) ? 1.f : prior[row * 512 + col2];
                            xs[row * XS_LD + col2] = z2 * p2;
                        }
                    }
                });
        }
        __syncthreads();

        // sparsemax (Newton on tau) + prior update; warp w -> rows 4w..4w+3
        {
            const int wid = tid >> 5, lane = tid & 31;
            const int mm0 = wid << 2;
            for (int r = 0; r < 4; r++) {
                const int row = mm0 + r;
                const float4* zp = reinterpret_cast<const float4*>(xs + row * XS_LD);
                float4 zv[4];
#pragma unroll
                for (int j = 0; j < 4; j++) zv[j] = zp[lane + 32 * j];
                float ssum = 0.f;
#pragma unroll
                for (int j = 0; j < 4; j++) ssum += zv[j].x + zv[j].y + zv[j].z + zv[j].w;
#pragma unroll
                for (int off = 16; off; off >>= 1)
                    ssum += __shfl_xor_sync(0xffffffffu, ssum, off);
                float tau = (ssum - 1.f) * (1.f / 512.f);
                for (int it = 0; it < 64; it++) {
                    float sb = 0.f, cb = 0.f;
#pragma unroll
                    for (int j = 0; j < 4; j++) {
                        float d;
                        d = zv[j].x - tau; if (d > 0.f) { sb += d; cb += 1.f; }
                        d = zv[j].y - tau; if (d > 0.f) { sb += d; cb += 1.f; }
                        d = zv[j].z - tau; if (d > 0.f) { sb += d; cb += 1.f; }
                        d = zv[j].w - tau; if (d > 0.f) { sb += d; cb += 1.f; }
                    }
#pragma unroll
                    for (int off = 16; off; off >>= 1) {
                        sb += __shfl_xor_sync(0xffffffffu, sb, off);
                        cb += __shfl_xor_sync(0xffffffffu, cb, off);
                    }
                    float tn = tau + (sb - 1.f) / cb;
                    if (!(tn > tau)) break;
                    tau = tn;
                }
                float4* pp = reinterpret_cast<float4*>(prior + row * 512);
#pragma unroll
                for (int j = 0; j < 4; j++) {
                    float4 pv = (s == 0) ? make_float4(1.f, 1.f, 1.f, 1.f)
                                         : pp[lane + 32 * j];
                    float4 o;
                    o.x = pv.x * (GAMMA_C - fmaxf(zv[j].x - tau, 0.f));
                    o.y = pv.y * (GAMMA_C - fmaxf(zv[j].y - tau, 0.f));
                    o.z = pv.z * (GAMMA_C - fmaxf(zv[j].z - tau, 0.f));
                    o.w = pv.w * (GAMMA_C - fmaxf(zv[j].w - tau, 0.f));
                    pp[lane + 32 * j] = o;
                }
            }
        }
        __syncthreads();
    }

    __syncthreads();
    // final: out = agg @ fW + fb
    if (tid < 64) {
        int m = tid >> 1, o = tid & 1;
        float acc = fb[o];
#pragma unroll
        for (int j = 0; j < 64; j++) acc = fmaf(aggs[m * 64 + j], fW[j * 2 + o], acc);
        out[(size_t)(row0 + m) * 2 + o] = acc;
    }
}

extern "C" void kernel_launch(void* const* d_in, const int* in_sizes, int n_in,
                              void* d_out, int out_size)
{
    const float* x    = (const float*)d_in[0];
    const float* bn0g = (const float*)d_in[1];
    const float* bn0b = (const float*)d_in[2];
    const float* bn0m = (const float*)d_in[3];
    const float* bn0v = (const float*)d_in[4];
    const float* shW  = (const float*)d_in[5];
    const float* shg  = (const float*)d_in[6];
    const float* shbp = (const float*)d_in[7];
    const float* shm  = (const float*)d_in[8];
    const float* shv  = (const float*)d_in[9];
    const float* stW  = (const float*)d_in[10];
    const float* stg  = (const float*)d_in[11];
    const float* stb  = (const float*)d_in[12];
    const float* stm  = (const float*)d_in[13];
    const float* stv  = (const float*)d_in[14];
    const float* atW  = (const float*)d_in[15];
    const float* atg  = (const float*)d_in[16];
    const float* atb  = (const float*)d_in[17];
    const float* atm  = (const float*)d_in[18];
    const float* atv  = (const float*)d_in[19];
    const float* fW   = (const float*)d_in[20];
    const float* fb   = (const float*)d_in[21];

    int Btot = in_sizes[0] / 512;
    int grid = Btot / 32;
    size_t smem = 52608 * sizeof(float);
    cudaFuncSetAttribute(tabnet_kernel,
                         cudaFuncAttributeMaxDynamicSharedMemorySize, (int)smem);
    tabnet_kernel<<<grid, 256, smem>>>(
        x, bn0g, bn0b, bn0m, bn0v,
        shW, shg, shbp, shm, shv,
        stW, stg, stb, stm, stv,
        atW, atg, atb, atm, atv,
        fW, fb, (float*)d_out);
}

// round 9
// speedup vs baseline: 1.8937x; 1.0062x over previous
#include <cuda_runtime.h>
#include <cstdint>
#include <math.h>

#define EPSI 1e-5f
#define GAMMA_C 1.3f

typedef unsigned long long u64t;

__device__ __forceinline__ u64t splat2(float a) {
    u64t r; asm("mov.b64 %0, {%1, %1};" : "=l"(r) : "f"(a)); return r;
}
__device__ __forceinline__ void fma2(u64t& d, u64t a, u64t b) {
    asm("fma.rn.f32x2 %0, %1, %2, %0;" : "+l"(d) : "l"(a), "l"(b));
}
__device__ __forceinline__ void unpack2(u64t v, float& lo, float& hi) {
    asm("mov.b64 {%0, %1}, %2;" : "=f"(lo), "=f"(hi) : "l"(v));
}
__device__ __forceinline__ void cp16(unsigned int dst, const void* src) {
    asm volatile("cp.async.cg.shared.global [%0], [%1], 16;" :: "r"(dst), "l"(src));
}

__device__ __forceinline__ float f4c(const float4& v, int i) {
    switch (i & 3) {
        case 0: return v.x;
        case 1: return v.y;
        case 2: return v.z;
        default: return v.w;
    }
}

// Block GEMM: C[32 x 256] = A[32 x KTOT] (smem, stride lda) * W[KTOT x 256]
// (global, row stride ldw). 256 threads, 8 warps, ONE block per SM.
// Warp w owns cols [16w,16w+16) and [128+16w,+16) -> GLU pairs in-warp.
// Each warp streams its OWN 32-col W slice through a warp-private smem double
// buffer (16-k chunks) with its own cp.async groups: NO __syncthreads in the
// mainloop. Thread tile: 8 rows x 4 cols; per k: 16 FFMA2.
// Register software pipeline: all A+W loads for 4-k group g+1 are issued
// before the 64 FFMA2 of group g (loads covered by ~128 issue cycles).
template <int KTOT, typename Epi>
__device__ __forceinline__ void gemm_tile(
    const float* __restrict__ As, int lda,
    const float* __restrict__ Wg, int ldw,
    float* __restrict__ wbuf, Epi epi)
{
    const int tid  = threadIdx.x;
    const int wid  = tid >> 5, lane = tid & 31;
    const int rp   = lane & 3, cp = lane >> 2;
    const int c0   = wid * 16 + cp * 2;
    constexpr int NCH = KTOT / 16;

    // warp-private double buffer: 2 stages x 512 floats (16 k x 32 cols)
    float* wb = wbuf + wid * 1024;
    const unsigned int wb_s = (unsigned int)__cvta_generic_to_shared(wb);

    const int seg0 = lane >> 2;   // 0..7
    const int part = lane & 3;

    u64t acc[8][2];
#pragma unroll
    for (int i = 0; i < 8; i++) { acc[i][0] = 0ull; acc[i][1] = 0ull; }

    auto load_chunk = [&](int ch, int stage) {
        const float* Wr = Wg + ch * 16 * ldw + wid * 16 + part * 4;
#pragma unroll
        for (int j = 0; j < 4; j++) {
            int seg = seg0 + 8 * j;            // 0..31
            int k = seg >> 1, half = seg & 1;
            cp16(wb_s + stage * 2048 + k * 128 + half * 64 + part * 16,
                 Wr + k * ldw + half * 128);
        }
        asm volatile("cp.async.commit_group;" ::: "memory");
    };

    load_chunk(0, 0);

    int cur = 0;
    for (int ch = 0; ch < NCH; ch++) {
        const bool more = (ch + 1 < NCH);
        if (more) {
            load_chunk(ch + 1, cur ^ 1);
            asm volatile("cp.async.wait_group 1;" ::: "memory");
        } else {
            asm volatile("cp.async.wait_group 0;" ::: "memory");
        }
        const float* wc = wb + cur * 512;
        const int kk = ch * 16;

        float4 abuf[2][8];
        u64t   wreg[2][4][2];

        // preload group 0
#pragma unroll
        for (int i = 0; i < 8; i++)
            abuf[0][i] = *reinterpret_cast<const float4*>(
                As + (rp + 4 * i) * lda + kk);
#pragma unroll
        for (int kz = 0; kz < 4; kz++) {
            wreg[0][kz][0] = *reinterpret_cast<const u64t*>(wc + kz * 32 + cp * 2);
            wreg[0][kz][1] = *reinterpret_cast<const u64t*>(wc + kz * 32 + 16 + cp * 2);
        }

#pragma unroll
        for (int k4 = 0; k4 < 4; k4++) {
            const int cb = k4 & 1;
            if (k4 < 3) {
                const int nb = cb ^ 1;
#pragma unroll
                for (int i = 0; i < 8; i++)
                    abuf[nb][i] = *reinterpret_cast<const float4*>(
                        As + (rp + 4 * i) * lda + kk + (k4 + 1) * 4);
                const float* wg4 = wc + (k4 + 1) * 4 * 32;
#pragma unroll
                for (int kz = 0; kz < 4; kz++) {
                    wreg[nb][kz][0] = *reinterpret_cast<const u64t*>(wg4 + kz * 32 + cp * 2);
                    wreg[nb][kz][1] = *reinterpret_cast<const u64t*>(wg4 + kz * 32 + 16 + cp * 2);
                }
            }
#pragma unroll
            for (int kz = 0; kz < 4; kz++) {
#pragma unroll
                for (int i = 0; i < 8; i++) {
                    u64t s = splat2(f4c(abuf[cb][i], kz));
                    fma2(acc[i][0], s, wreg[cb][kz][0]);
                    fma2(acc[i][1], s, wreg[cb][kz][1]);
                }
            }
        }
        cur ^= 1;
    }
    epi(rp, c0, acc);
}

#define XS_LD 516
#define SH_LD 132

__global__ __launch_bounds__(256, 1)
void tabnet_kernel(
    const float* __restrict__ x,
    const float* __restrict__ bn0_g, const float* __restrict__ bn0_b,
    const float* __restrict__ bn0_m, const float* __restrict__ bn0_v,
    const float* __restrict__ shW,
    const float* __restrict__ sh_g, const float* __restrict__ sh_b,
    const float* __restrict__ sh_m, const float* __restrict__ sh_v,
    const float* __restrict__ stW,
    const float* __restrict__ st_g, const float* __restrict__ st_b,
    const float* __restrict__ st_m, const float* __restrict__ st_v,
    const float* __restrict__ atW,
    const float* __restrict__ at_g, const float* __restrict__ at_b,
    const float* __restrict__ at_m, const float* __restrict__ at_v,
    const float* __restrict__ fW, const float* __restrict__ fb,
    float* __restrict__ out)
{
    extern __shared__ float smem[];
    float* xs    = smem;             // [32][516]  x tile, later z buffer
    float* prior = smem + 16512;     // [32][512]
    float* shb   = smem + 32896;     // [32][132]  GLU(shared step) output
    float* hg    = smem + 37120;     // [32][132]  GLU(step) output (h_d | h_a)
    float* aggs  = smem + 41344;     // [32][64]
    float* wbuf  = smem + 43392;     // 8 warps x 2 stages x 512 floats
    float* bnsc  = smem + 51584;     // [512]
    float* bnsh  = smem + 52096;     // [512]
    // total 52608 floats = 210432 bytes

    const int tid = threadIdx.x;
    const int row0 = blockIdx.x << 5;

    for (int i = tid; i < 2048; i += 256) aggs[i] = 0.f;

    for (int c = tid; c < 512; c += 256) {
        float sc = bn0_g[c] * rsqrtf(bn0_v[c] + EPSI);
        bnsc[c] = sc;
        bnsh[c] = bn0_b[c] - bn0_m[c] * sc;
    }
    __syncthreads();

    // load x tile + bn0
    {
        const float4* xg = reinterpret_cast<const float4*>(x) + (size_t)row0 * 128;
        const float4* s4 = reinterpret_cast<const float4*>(bnsc);
        const float4* b4 = reinterpret_cast<const float4*>(bnsh);
        float4* xs4 = reinterpret_cast<float4*>(xs);
#pragma unroll
        for (int i = 0; i < 16; i++) {
            int f = tid + 256 * i;
            int r = f >> 7, c4 = f & 127;
            float4 v = xg[f];
            float4 s = s4[c4], b = b4[c4];
            v.x = fmaf(v.x, s.x, b.x);
            v.y = fmaf(v.y, s.y, b.y);
            v.z = fmaf(v.z, s.z, b.z);
            v.w = fmaf(v.w, s.w, b.w);
            xs4[r * 129 + c4] = v;
        }
    }
    __syncthreads();

    // shared-step bn tables
    {
        int c = tid;
        float sc = sh_g[c] * rsqrtf(sh_v[c] + EPSI);
        bnsc[c] = sc;
        bnsh[c] = sh_b[c] - sh_m[c] * sc;
    }
    __syncthreads();   // bn tables visible to all warps' epilogues

    // GEMM1: sh = GLU(bn(x @ shW))
    gemm_tile<512>(xs, XS_LD, shW, 256, wbuf,
        [&](int rp, int c0, u64t (&acc)[8][2]) {
#pragma unroll
            for (int i = 0; i < 8; i++) {
                int row = rp + 4 * i;
                float u[2], w[2];
                unpack2(acc[i][0], u[0], u[1]);
                unpack2(acc[i][1], w[0], w[1]);
#pragma unroll
                for (int t = 0; t < 2; t++) {
                    int cu = c0 + t, cw = c0 + 128 + t;
                    float uu = fmaf(u[t], bnsc[cu], bnsh[cu]);
                    float ww = fmaf(w[t], bnsc[cw], bnsh[cw]);
                    shb[row * SH_LD + cu] = uu / (1.f + __expf(-ww));
                }
            }
        });
    __syncthreads();

    for (int s = 0; s < 3; s++) {
        {
            int c = tid;
            float sc = st_g[s * 256 + c] * rsqrtf(st_v[s * 256 + c] + EPSI);
            bnsc[c] = sc;
            bnsh[c] = st_b[s * 256 + c] - st_m[s * 256 + c] * sc;
        }
        __syncthreads();
        // GEMM2: h = GLU(bn(sh @ stW[s])); agg += h_d
        gemm_tile<128>(shb, SH_LD, stW + s * 128 * 256, 256, wbuf,
            [&](int rp, int c0, u64t (&acc)[8][2]) {
#pragma unroll
                for (int i = 0; i < 8; i++) {
                    int row = rp + 4 * i;
                    float u[2], w[2];
                    unpack2(acc[i][0], u[0], u[1]);
                    unpack2(acc[i][1], w[0], w[1]);
#pragma unroll
                    for (int t = 0; t < 2; t++) {
                        int cu = c0 + t, cw = c0 + 128 + t;
                        float uu = fmaf(u[t], bnsc[cu], bnsh[cu]);
                        float ww = fmaf(w[t], bnsc[cw], bnsh[cw]);
                        float val = uu / (1.f + __expf(-ww));
                        hg[row * SH_LD + cu] = val;
                        if (c0 < 64) aggs[row * 64 + cu] += val;
                    }
                }
            });
        __syncthreads();
        if (s == 2) break;  // last step's attention/sparsemax/prior are dead code

        for (int c = tid; c < 512; c += 256) {
            float sc = at_g[s * 512 + c] * rsqrtf(at_v[s * 512 + c] + EPSI);
            bnsc[c] = sc;
            bnsh[c] = at_b[s * 512 + c] - at_m[s * 512 + c] * sc;
        }
        __syncthreads();
        // GEMM3: z = bn(h_a @ atW[s]) * prior -> xs
        for (int half = 0; half < 2; half++) {
            const int cbase = half * 256;
            gemm_tile<64>(hg + 64, SH_LD, atW + s * 64 * 512 + cbase, 512, wbuf,
                [&](int rp, int c0, u64t (&acc)[8][2]) {
#pragma unroll
                    for (int i = 0; i < 8; i++) {
                        int row = rp + 4 * i;
                        float u[2], w[2];
                        unpack2(acc[i][0], u[0], u[1]);
                        unpack2(acc[i][1], w[0], w[1]);
#pragma unroll
                        for (int t = 0; t < 2; t++) {
                            int col = cbase + c0 + t;
                            float z = fmaf(u[t], bnsc[col], bnsh[col]);
                            float p = (s == 0) ? 1.f : prior[row * 512 + col];
                            xs[row * XS_LD + col] = z * p;
                            int col2 = cbase + c0 + 128 + t;
                            float z2 = fmaf(w[t], bnsc[col2], bnsh[col2]);
                            float p2 = (s == 0) ? 1.f : prior[row * 512 + col2];
                            xs[row * XS_LD + col2] = z2 * p2;
                        }
                    }
                });
        }
        __syncthreads();

        // sparsemax (Newton on tau) + prior update; warp w -> rows 4w..4w+3
        {
            const int wid = tid >> 5, lane = tid & 31;
            const int mm0 = wid << 2;
            for (int r = 0; r < 4; r++) {
                const int row = mm0 + r;
                const float4* zp = reinterpret_cast<const float4*>(xs + row * XS_LD);
                float4 zv[4];
#pragma unroll
                for (int j = 0; j < 4; j++) zv[j] = zp[lane + 32 * j];
                float ssum = 0.f;
#pragma unroll
                for (int j = 0; j < 4; j++) ssum += zv[j].x + zv[j].y + zv[j].z + zv[j].w;
#pragma unroll
                for (int off = 16; off; off >>= 1)
                    ssum += __shfl_xor_sync(0xffffffffu, ssum, off);
                float tau = (ssum - 1.f) * (1.f / 512.f);
                for (int it = 0; it < 64; it++) {
                    float sb = 0.f, cb = 0.f;
#pragma unroll
                    for (int j = 0; j < 4; j++) {
                        float d;
                        d = zv[j].x - tau; if (d > 0.f) { sb += d; cb += 1.f; }
                        d = zv[j].y - tau; if (d > 0.f) { sb += d; cb += 1.f; }
                        d = zv[j].z - tau; if (d > 0.f) { sb += d; cb += 1.f; }
                        d = zv[j].w - tau; if (d > 0.f) { sb += d; cb += 1.f; }
                    }
#pragma unroll
                    for (int off = 16; off; off >>= 1) {
                        sb += __shfl_xor_sync(0xffffffffu, sb, off);
                        cb += __shfl_xor_sync(0xffffffffu, cb, off);
                    }
                    float tn = tau + (sb - 1.f) / cb;
                    if (!(tn > tau)) break;
                    tau = tn;
                }
                float4* pp = reinterpret_cast<float4*>(prior + row * 512);
#pragma unroll
                for (int j = 0; j < 4; j++) {
                    float4 pv = (s == 0) ? make_float4(1.f, 1.f, 1.f, 1.f)
                                         : pp[lane + 32 * j];
                    float4 o;
                    o.x = pv.x * (GAMMA_C - fmaxf(zv[j].x - tau, 0.f));
                    o.y = pv.y * (GAMMA_C - fmaxf(zv[j].y - tau, 0.f));
                    o.z = pv.z * (GAMMA_C - fmaxf(zv[j].z - tau, 0.f));
                    o.w = pv.w * (GAMMA_C - fmaxf(zv[j].w - tau, 0.f));
                    pp[lane + 32 * j] = o;
                }
            }
        }
        __syncthreads();
    }

    __syncthreads();
    // final: out = agg @ fW + fb
    if (tid < 64) {
        int m = tid >> 1, o = tid & 1;
        float acc = fb[o];
#pragma unroll
        for (int j = 0; j < 64; j++) acc = fmaf(aggs[m * 64 + j], fW[j * 2 + o], acc);
        out[(size_t)(row0 + m) * 2 + o] = acc;
    }
}

extern "C" void kernel_launch(void* const* d_in, const int* in_sizes, int n_in,
                              void* d_out, int out_size)
{
    const float* x    = (const float*)d_in[0];
    const float* bn0g = (const float*)d_in[1];
    const float* bn0b = (const float*)d_in[2];
    const float* bn0m = (const float*)d_in[3];
    const float* bn0v = (const float*)d_in[4];
    const float* shW  = (const float*)d_in[5];
    const float* shg  = (const float*)d_in[6];
    const float* shbp = (const float*)d_in[7];
    const float* shm  = (const float*)d_in[8];
    const float* shv  = (const float*)d_in[9];
    const float* stW  = (const float*)d_in[10];
    const float* stg  = (const float*)d_in[11];
    const float* stb  = (const float*)d_in[12];
    const float* stm  = (const float*)d_in[13];
    const float* stv  = (const float*)d_in[14];
    const float* atW  = (const float*)d_in[15];
    const float* atg  = (const float*)d_in[16];
    const float* atb  = (const float*)d_in[17];
    const float* atm  = (const float*)d_in[18];
    const float* atv  = (const float*)d_in[19];
    const float* fW   = (const float*)d_in[20];
    const float* fb   = (const float*)d_in[21];

    int Btot = in_sizes[0] / 512;
    int grid = Btot / 32;
    size_t smem = 52608 * sizeof(float);
    cudaFuncSetAttribute(tabnet_kernel,
                         cudaFuncAttributeMaxDynamicSharedMemorySize, (int)smem);
    tabnet_kernel<<<grid, 256, smem>>>(
        x, bn0g, bn0b, bn0m, bn0v,
        shW, shg, shbp, shm, shv,
        stW, stg, stb, stm, stv,
        atW, atg, atb, atm, atv,
        fW, fb, (float*)d_out);
}

// round 10
// speedup vs baseline: 3.7746x; 1.9932x over previous
#include <cuda_runtime.h>
#include <cstdint>
#include <math.h>

#define EPSI 1e-5f

typedef unsigned long long u64t;

__device__ __forceinline__ u64t splat2(float a) {
    u64t r; asm("mov.b64 %0, {%1, %1};" : "=l"(r) : "f"(a)); return r;
}
__device__ __forceinline__ void fma2(u64t& d, u64t a, u64t b) {
    asm("fma.rn.f32x2 %0, %1, %2, %0;" : "+l"(d) : "l"(a), "l"(b));
}
__device__ __forceinline__ void unpack2(u64t v, float& lo, float& hi) {
    asm("mov.b64 {%0, %1}, %2;" : "=f"(lo), "=f"(hi) : "l"(v));
}
__device__ __forceinline__ void cp16(unsigned int dst, const void* src) {
    asm volatile("cp.async.cg.shared.global [%0], [%1], 16;" :: "r"(dst), "l"(src));
}

__device__ __forceinline__ float f4c(const float4& v, int i) {
    switch (i & 3) {
        case 0: return v.x;
        case 1: return v.y;
        case 2: return v.z;
        default: return v.w;
    }
}

// Full-width block GEMM: C[32 x 256] = A[32 x KTOT] (smem) * W[KTOT x 256].
// 256 threads, 8 warps. Warp w owns cols [16w,+16) and [128+16w,+16).
// Warp-private smem double buffer, no __syncthreads in mainloop.
// Thread tile 8 rows x 4 cols; per k: 16 FFMA2.
template <int KTOT, typename Epi>
__device__ __forceinline__ void gemm_tile(
    const float* __restrict__ As, int lda,
    const float* __restrict__ Wg, int ldw,
    float* __restrict__ wbuf, Epi epi)
{
    const int tid  = threadIdx.x;
    const int wid  = tid >> 5, lane = tid & 31;
    const int rp   = lane & 3, cp = lane >> 2;
    const int c0   = wid * 16 + cp * 2;
    constexpr int NCH = KTOT / 16;

    float* wb = wbuf + wid * 1024;
    const unsigned int wb_s = (unsigned int)__cvta_generic_to_shared(wb);
    const int seg0 = lane >> 2;
    const int part = lane & 3;

    u64t acc[8][2];
#pragma unroll
    for (int i = 0; i < 8; i++) { acc[i][0] = 0ull; acc[i][1] = 0ull; }

    auto load_chunk = [&](int ch, int stage) {
        const float* Wr = Wg + ch * 16 * ldw + wid * 16 + part * 4;
#pragma unroll
        for (int j = 0; j < 4; j++) {
            int seg = seg0 + 8 * j;
            int k = seg >> 1, half = seg & 1;
            cp16(wb_s + stage * 2048 + k * 128 + half * 64 + part * 16,
                 Wr + k * ldw + half * 128);
        }
        asm volatile("cp.async.commit_group;" ::: "memory");
    };

    load_chunk(0, 0);

    int cur = 0;
    for (int ch = 0; ch < NCH; ch++) {
        const bool more = (ch + 1 < NCH);
        if (more) {
            load_chunk(ch + 1, cur ^ 1);
            asm volatile("cp.async.wait_group 1;" ::: "memory");
        } else {
            asm volatile("cp.async.wait_group 0;" ::: "memory");
        }
        const float* wc = wb + cur * 512;
        const int kk = ch * 16;
#pragma unroll
        for (int k4 = 0; k4 < 4; k4++) {
            float4 a[8];
#pragma unroll
            for (int i = 0; i < 8; i++)
                a[i] = *reinterpret_cast<const float4*>(
                    As + (rp + 4 * i) * lda + kk + k4 * 4);
#pragma unroll
            for (int kz = 0; kz < 4; kz++) {
                const float* wr = wc + (k4 * 4 + kz) * 32;
                u64t w0 = *reinterpret_cast<const u64t*>(wr + cp * 2);
                u64t w1 = *reinterpret_cast<const u64t*>(wr + 16 + cp * 2);
#pragma unroll
                for (int i = 0; i < 8; i++) {
                    u64t s = splat2(f4c(a[i], kz));
                    fma2(acc[i][0], s, w0);
                    fma2(acc[i][1], s, w1);
                }
            }
        }
        cur ^= 1;
    }
    epi(rp, c0, acc);
}

// Half-width block GEMM: only output cols {0..63} U {128..191} are live
// (GLU pairs producing h_d). 8 warps = 2 row-groups x 4 col-groups:
// warp w: grp = w>>2 (rows 16*grp..+16), w4 = w&3 (cols [16*w4,+16) U [128+16w4,+16)).
// Thread tile 4 rows x 4 cols; per k: 8 FFMA2.
template <int KTOT, typename Epi>
__device__ __forceinline__ void gemm_tile_half(
    const float* __restrict__ As, int lda,
    const float* __restrict__ Wg, int ldw,
    float* __restrict__ wbuf, Epi epi)
{
    const int tid  = threadIdx.x;
    const int wid  = tid >> 5, lane = tid & 31;
    const int w4   = wid & 3, grp = wid >> 2;
    const int rp   = lane & 3, cp = lane >> 2;
    const int c0   = w4 * 16 + cp * 2;
    const int rbase = grp * 16 + rp;
    constexpr int NCH = KTOT / 16;

    float* wb = wbuf + wid * 1024;
    const unsigned int wb_s = (unsigned int)__cvta_generic_to_shared(wb);
    const int seg0 = lane >> 2;
    const int part = lane & 3;

    u64t acc[4][2];
#pragma unroll
    for (int i = 0; i < 4; i++) { acc[i][0] = 0ull; acc[i][1] = 0ull; }

    auto load_chunk = [&](int ch, int stage) {
        const float* Wr = Wg + ch * 16 * ldw + w4 * 16 + part * 4;
#pragma unroll
        for (int j = 0; j < 4; j++) {
            int seg = seg0 + 8 * j;
            int k = seg >> 1, half = seg & 1;
            cp16(wb_s + stage * 2048 + k * 128 + half * 64 + part * 16,
                 Wr + k * ldw + half * 128);
        }
        asm volatile("cp.async.commit_group;" ::: "memory");
    };

    load_chunk(0, 0);

    int cur = 0;
    for (int ch = 0; ch < NCH; ch++) {
        const bool more = (ch + 1 < NCH);
        if (more) {
            load_chunk(ch + 1, cur ^ 1);
            asm volatile("cp.async.wait_group 1;" ::: "memory");
        } else {
            asm volatile("cp.async.wait_group 0;" ::: "memory");
        }
        const float* wc = wb + cur * 512;
        const int kk = ch * 16;
#pragma unroll
        for (int k4 = 0; k4 < 4; k4++) {
            float4 a[4];
#pragma unroll
            for (int i = 0; i < 4; i++)
                a[i] = *reinterpret_cast<const float4*>(
                    As + (rbase + 4 * i) * lda + kk + k4 * 4);
#pragma unroll
            for (int kz = 0; kz < 4; kz++) {
                const float* wr = wc + (k4 * 4 + kz) * 32;
                u64t w0 = *reinterpret_cast<const u64t*>(wr + cp * 2);
                u64t w1 = *reinterpret_cast<const u64t*>(wr + 16 + cp * 2);
#pragma unroll
                for (int i = 0; i < 4; i++) {
                    u64t s = splat2(f4c(a[i], kz));
                    fma2(acc[i][0], s, w0);
                    fma2(acc[i][1], s, w1);
                }
            }
        }
        cur ^= 1;
    }
    epi(rbase, c0, acc);
}

#define XS_LD 516
#define SH_LD 132

__global__ __launch_bounds__(256, 1)
void tabnet_kernel(
    const float* __restrict__ x,
    const float* __restrict__ bn0_g, const float* __restrict__ bn0_b,
    const float* __restrict__ bn0_m, const float* __restrict__ bn0_v,
    const float* __restrict__ shW,
    const float* __restrict__ sh_g, const float* __restrict__ sh_b,
    const float* __restrict__ sh_m, const float* __restrict__ sh_v,
    const float* __restrict__ stW,
    const float* __restrict__ st_g, const float* __restrict__ st_b,
    const float* __restrict__ st_m, const float* __restrict__ st_v,
    const float* __restrict__ fW, const float* __restrict__ fb,
    float* __restrict__ out)
{
    extern __shared__ float smem[];
    float* xs    = smem;             // [32][516]  x tile (GEMM1 A)
    float* shb   = smem + 16512;     // [32][132]  GLU(shared step) output
    float* aggs  = smem + 20736;     // [32][64]
    float* wbuf  = smem + 22784;     // 8 warps x 2 stages x 512 floats
    float* bnsc  = smem + 30976;     // [512]
    float* bnsh  = smem + 31488;     // [512]
    // total 32000 floats = 128000 bytes

    const int tid = threadIdx.x;
    const int row0 = blockIdx.x << 5;

    for (int c = tid; c < 512; c += 256) {
        float sc = bn0_g[c] * rsqrtf(bn0_v[c] + EPSI);
        bnsc[c] = sc;
        bnsh[c] = bn0_b[c] - bn0_m[c] * sc;
    }
    __syncthreads();

    // load x tile + bn0
    {
        const float4* xg = reinterpret_cast<const float4*>(x) + (size_t)row0 * 128;
        const float4* s4 = reinterpret_cast<const float4*>(bnsc);
        const float4* b4 = reinterpret_cast<const float4*>(bnsh);
        float4* xs4 = reinterpret_cast<float4*>(xs);
#pragma unroll
        for (int i = 0; i < 16; i++) {
            int f = tid + 256 * i;
            int r = f >> 7, c4 = f & 127;
            float4 v = xg[f];
            float4 s = s4[c4], b = b4[c4];
            v.x = fmaf(v.x, s.x, b.x);
            v.y = fmaf(v.y, s.y, b.y);
            v.z = fmaf(v.z, s.z, b.z);
            v.w = fmaf(v.w, s.w, b.w);
            xs4[r * 129 + c4] = v;
        }
    }
    __syncthreads();

    // shared-step bn tables
    {
        int c = tid;
        float sc = sh_g[c] * rsqrtf(sh_v[c] + EPSI);
        bnsc[c] = sc;
        bnsh[c] = sh_b[c] - sh_m[c] * sc;
    }
    __syncthreads();

    // GEMM1: sh = GLU(bn(x @ shW))
    gemm_tile<512>(xs, XS_LD, shW, 256, wbuf,
        [&](int rp, int c0, u64t (&acc)[8][2]) {
#pragma unroll
            for (int i = 0; i < 8; i++) {
                int row = rp + 4 * i;
                float u[2], w[2];
                unpack2(acc[i][0], u[0], u[1]);
                unpack2(acc[i][1], w[0], w[1]);
#pragma unroll
                for (int t = 0; t < 2; t++) {
                    int cu = c0 + t, cw = c0 + 128 + t;
                    float uu = fmaf(u[t], bnsc[cu], bnsh[cu]);
                    float ww = fmaf(w[t], bnsc[cw], bnsh[cw]);
                    shb[row * SH_LD + cu] = uu / (1.f + __expf(-ww));
                }
            }
        });
    __syncthreads();

    // agg accumulated in registers: thread owns 4 rows x 2 cols (all cols < 64)
    float agg[4][2];
#pragma unroll
    for (int i = 0; i < 4; i++) { agg[i][0] = 0.f; agg[i][1] = 0.f; }

    for (int s = 0; s < 3; s++) {
        {
            int c = tid;
            float sc = st_g[s * 256 + c] * rsqrtf(st_v[s * 256 + c] + EPSI);
            bnsc[c] = sc;
            bnsh[c] = st_b[s * 256 + c] - st_m[s * 256 + c] * sc;
        }
        __syncthreads();
        // GEMM2 (half): h_d = GLU(bn(sh @ stW[s]))[:, :64]; agg += h_d
        gemm_tile_half<128>(shb, SH_LD, stW + s * 128 * 256, 256, wbuf,
            [&](int rb, int c0, u64t (&acc)[4][2]) {
#pragma unroll
                for (int i = 0; i < 4; i++) {
                    float u[2], w[2];
                    unpack2(acc[i][0], u[0], u[1]);
                    unpack2(acc[i][1], w[0], w[1]);
#pragma unroll
                    for (int t = 0; t < 2; t++) {
                        int cu = c0 + t, cw = c0 + 128 + t;
                        float uu = fmaf(u[t], bnsc[cu], bnsh[cu]);
                        float ww = fmaf(w[t], bnsc[cw], bnsh[cw]);
                        agg[i][t] += uu / (1.f + __expf(-ww));
                    }
                }
            });
        __syncthreads();
    }

    // write agg registers to smem
    {
        const int wid = tid >> 5, lane = tid & 31;
        const int w4 = wid & 3, grp = wid >> 2;
        const int rp = lane & 3, cp = lane >> 2;
        const int c0 = w4 * 16 + cp * 2;
        const int rb = grp * 16 + rp;
#pragma unroll
        for (int i = 0; i < 4; i++) {
            aggs[(rb + 4 * i) * 64 + c0]     = agg[i][0];
            aggs[(rb + 4 * i) * 64 + c0 + 1] = agg[i][1];
        }
    }
    __syncthreads();

    // final: out = agg @ fW + fb
    if (tid < 64) {
        int m = tid >> 1, o = tid & 1;
        float acc = fb[o];
#pragma unroll
        for (int j = 0; j < 64; j++) acc = fmaf(aggs[m * 64 + j], fW[j * 2 + o], acc);
        out[(size_t)(row0 + m) * 2 + o] = acc;
    }
}

extern "C" void kernel_launch(void* const* d_in, const int* in_sizes, int n_in,
                              void* d_out, int out_size)
{
    const float* x    = (const float*)d_in[0];
    const float* bn0g = (const float*)d_in[1];
    const float* bn0b = (const float*)d_in[2];
    const float* bn0m = (const float*)d_in[3];
    const float* bn0v = (const float*)d_in[4];
    const float* shW  = (const float*)d_in[5];
    const float* shg  = (const float*)d_in[6];
    const float* shbp = (const float*)d_in[7];
    const float* shm  = (const float*)d_in[8];
    const float* shv  = (const float*)d_in[9];
    const float* stW  = (const float*)d_in[10];
    const float* stg  = (const float*)d_in[11];
    const float* stb  = (const float*)d_in[12];
    const float* stm  = (const float*)d_in[13];
    const float* stv  = (const float*)d_in[14];
    const float* fW   = (const float*)d_in[20];
    const float* fb   = (const float*)d_in[21];

    int Btot = in_sizes[0] / 512;
    int grid = Btot / 32;
    size_t smem = 32000 * sizeof(float);
    cudaFuncSetAttribute(tabnet_kernel,
                         cudaFuncAttributeMaxDynamicSharedMemorySize, (int)smem);
    tabnet_kernel<<<grid, 256, smem>>>(
        x, bn0g, bn0b, bn0m, bn0v,
        shW, shg, shbp, shm, shv,
        stW, stg, stb, stm, stv,
        fW, fb, (float*)d_out);
}